// round 9
// baseline (speedup 1.0000x reference)
#include <cuda_runtime.h>
#include <cuda_bf16.h>
#include <cstdint>

// ---------------------------------------------------------------------------
// Wav2Vec2 Gumbel VQ via mma.sync bf16 (sm_100 baseline path).
//   logits = h @ W + b with bf16x3 split, 6 products (fp32-quality).
//   256-thread CTAs, tile 64x320 (full group), warp tile 32x80, 2 CTAs/SM.
//   A double-buffered, B single-buffered. Fused argmax+histogram+gather.
// ---------------------------------------------------------------------------

namespace {
constexpr int kBT = 65536;
constexpr int kH  = 512;
constexpr int kV  = 320;
constexpr int kG  = 2;
constexpr int kGV = kG * kV;

constexpr int kMT = 64;                   // tokens per CTA
constexpr int kNT = 320;                  // logit cols per CTA (full group)
constexpr int kKC = 32;                   // K per chunk (2 mma k-steps)
constexpr int kChunks = kH / kKC;         // 16
constexpr int kThr = 256;                 // threads per CTA (8 warps)

constexpr uint32_t kRowB   = 80;                           // 32 bf16 + 16B pad
constexpr uint32_t kAterm  = kMT * kRowB;                  // 5120
constexpr uint32_t kBterm  = kNT * kRowB;                  // 25600
constexpr uint32_t kAbuf   = 3 * kAterm;                   // 15360 (one stage)
constexpr uint32_t kBbuf   = 3 * kBterm;                   // 76800 (single)
constexpr uint32_t kHdr    = 3584;        // red_val|red_idx|idx_s|bias_s
constexpr uint32_t kSmemBytes = kHdr + 2 * kAbuf + kBbuf;  // 111104 (x2 <= 228K)
}  // namespace

// global scratch (no cudaMalloc allowed)
__device__ __align__(256) __nv_bfloat16 g_h1[(size_t)kBT * kH];
__device__ __align__(256) __nv_bfloat16 g_h2[(size_t)kBT * kH];
__device__ __align__(256) __nv_bfloat16 g_h3[(size_t)kBT * kH];
__device__ __align__(256) __nv_bfloat16 g_w1t[kGV * kH];
__device__ __align__(256) __nv_bfloat16 g_w2t[kGV * kH];
__device__ __align__(256) __nv_bfloat16 g_w3t[kGV * kH];
__device__ int g_counts[kGV];

// ---------------- PTX helpers ----------------
__device__ __forceinline__ uint32_t smem_u32(const void* p) {
    uint32_t a;
    asm("{ .reg .u64 t; cvta.to.shared.u64 t, %1; cvt.u32.u64 %0, t; }"
        : "=r"(a) : "l"(p));
    return a;
}
__device__ __forceinline__ void cpa16(uint32_t s, const void* g) {
    asm volatile("cp.async.cg.shared.global [%0], [%1], 16;" :: "r"(s), "l"(g));
}
__device__ __forceinline__ void cpa_commit() {
    asm volatile("cp.async.commit_group;" ::: "memory");
}
__device__ __forceinline__ void ldsm4(uint32_t* d, uint32_t addr) {
    asm volatile("ldmatrix.sync.aligned.m8n8.x4.shared.b16 {%0,%1,%2,%3}, [%4];"
                 : "=r"(d[0]), "=r"(d[1]), "=r"(d[2]), "=r"(d[3]) : "r"(addr));
}
__device__ __forceinline__ void mma16816(float* c, const uint32_t* a,
                                         uint32_t b0, uint32_t b1) {
    asm volatile(
        "mma.sync.aligned.m16n8k16.row.col.f32.bf16.bf16.f32 "
        "{%0,%1,%2,%3}, {%4,%5,%6,%7}, {%8,%9}, {%0,%1,%2,%3};"
        : "+f"(c[0]), "+f"(c[1]), "+f"(c[2]), "+f"(c[3])
        : "r"(a[0]), "r"(a[1]), "r"(a[2]), "r"(a[3]), "r"(b0), "r"(b1));
}

// ---------------- split kernels ----------------
__device__ __forceinline__ uint32_t pk2(__nv_bfloat16 x, __nv_bfloat16 y) {
    return (uint32_t)__bfloat16_as_ushort(x) |
           ((uint32_t)__bfloat16_as_ushort(y) << 16);
}

__global__ void __launch_bounds__(256) split_h_kernel(const float* __restrict__ h) {
    size_t i = (size_t)blockIdx.x * 256 + threadIdx.x;   // one float4 each
    float4 x = ((const float4*)h)[i];
    float v[4] = {x.x, x.y, x.z, x.w};
    __nv_bfloat16 a[4], b[4], c[4];
#pragma unroll
    for (int j = 0; j < 4; j++) {
        a[j] = __float2bfloat16_rn(v[j]);
        float r = v[j] - __bfloat162float(a[j]);
        b[j] = __float2bfloat16_rn(r);
        float r2 = r - __bfloat162float(b[j]);
        c[j] = __float2bfloat16_rn(r2);
    }
    ((uint2*)g_h1)[i] = make_uint2(pk2(a[0], a[1]), pk2(a[2], a[3]));
    ((uint2*)g_h2)[i] = make_uint2(pk2(b[0], b[1]), pk2(b[2], b[3]));
    ((uint2*)g_h3)[i] = make_uint2(pk2(c[0], c[1]), pk2(c[2], c[3]));
}

__global__ void __launch_bounds__(256) split_w_kernel(const float* __restrict__ W) {
    int idx = blockIdx.x * 256 + threadIdx.x;   // over 512*640
    int k = idx / kGV;
    int n = idx - k * kGV;
    float v = W[idx];
    __nv_bfloat16 a = __float2bfloat16_rn(v);
    float r = v - __bfloat162float(a);
    __nv_bfloat16 b = __float2bfloat16_rn(r);
    float r2 = r - __bfloat162float(b);
    __nv_bfloat16 c = __float2bfloat16_rn(r2);
    size_t o = (size_t)n * kH + k;               // transposed [n][k]
    g_w1t[o] = a; g_w2t[o] = b; g_w3t[o] = c;
}

// ---------------- main tensor kernel loaders ----------------
__device__ __forceinline__ void load_A(int c, int m0, uint32_t dst, int tid) {
    // 3 terms x 64 rows x 4 x 16B = 768 cp.async (3 per thread)
#pragma unroll
    for (int t = 0; t < 3; ++t) {
        const __nv_bfloat16* hp = (t == 0) ? g_h1 : (t == 1) ? g_h2 : g_h3;
        int row = tid >> 2, cs = tid & 3;
        const void* gp = hp + ((size_t)(m0 + row) * kH + c * kKC + cs * 8);
        cpa16(dst + t * kAterm + row * kRowB + cs * 16, gp);
    }
}

__device__ __forceinline__ void load_B(int c, int nbase, uint32_t dst, int tid) {
    // 3 terms x 320 rows x 4 x 16B = 3840 cp.async (15 per thread)
#pragma unroll
    for (int t = 0; t < 3; ++t) {
        const __nv_bfloat16* wp = (t == 0) ? g_w1t : (t == 1) ? g_w2t : g_w3t;
#pragma unroll
        for (int i = 0; i < 5; ++i) {
            int idx = tid + i * kThr;        // 0..1279
            int row = idx >> 2, cs = idx & 3;
            const void* gp = wp + ((size_t)(nbase + row) * kH + c * kKC + cs * 8);
            cpa16(dst + t * kBterm + row * kRowB + cs * 16, gp);
        }
    }
}

__global__ void __launch_bounds__(kThr, 2)
vq_mma(const float* __restrict__ bias,
       const float* __restrict__ cb,      // [640][128]
       float* __restrict__ out)           // [BT][256]
{
    extern __shared__ __align__(256) char smem_raw[];
    const uint32_t sbase = smem_u32(smem_raw);
    float* red_val = (float*)smem_raw;                 // [64][4]
    int*   red_idx = (int*)(smem_raw + 1024);          // [64][4]
    int*   idx_s   = (int*)(smem_raw + 2048);          // [64]
    float* bias_s  = (float*)(smem_raw + 2304);        // [320]
    const uint32_t A0 = sbase + kHdr;                  // A buf 0
    const uint32_t A1 = A0 + kAbuf;                    // A buf 1
    const uint32_t Bs = A1 + kAbuf;                    // single B buf

    const int tid  = threadIdx.x;
    const int warp = tid >> 5;
    const int lane = tid & 31;
    const int mw   = warp >> 2;            // 0..1 (32 rows each)
    const int nw   = warp & 3;             // 0..3 (80 cols each)
    const int gID  = lane >> 2;
    const int tig  = lane & 3;
    const int g    = blockIdx.x & 1;
    const int m0   = (blockIdx.x >> 1) * kMT;
    const int nbase = g * kV;              // B row base (full group)

    for (int i = tid; i < kNT; i += kThr) bias_s[i] = bias[nbase + i];

    // prologue: group0 = A0+B0, group1 = A1
    load_A(0, m0, A0, tid);
    load_B(0, nbase, Bs, tid);
    cpa_commit();
    load_A(1, m0, A1, tid);
    cpa_commit();

    float acc[2][10][4];
#pragma unroll
    for (int mf = 0; mf < 2; ++mf)
#pragma unroll
        for (int nf = 0; nf < 10; ++nf)
#pragma unroll
            for (int q = 0; q < 4; ++q) acc[mf][nf][q] = 0.f;

    const int g2 = lane >> 3, rr = lane & 7;

    for (int c = 0; c < kChunks; ++c) {
        if (c < kChunks - 1)
            asm volatile("cp.async.wait_group 1;" ::: "memory");
        else
            asm volatile("cp.async.wait_group 0;" ::: "memory");
        __syncthreads();

        const uint32_t Ts = (c & 1) ? A1 : A0;

#pragma unroll
        for (int ks = 0; ks < 2; ++ks) {
            const uint32_t arow = (uint32_t)(mw * 32 + (g2 & 1) * 8 + rr);
            const uint32_t koA  = (uint32_t)(ks * 32 + (g2 >> 1) * 16);
            const uint32_t brow = (uint32_t)(nw * 80 + (g2 >> 1) * 8 + rr);
            const uint32_t koB  = (uint32_t)(ks * 32 + (g2 & 1) * 16);

            // at-outer: only ONE a-term live (8 regs) to fit 128-reg budget
#pragma unroll
            for (int at = 0; at < 3; ++at) {
                uint32_t a[2][4];
#pragma unroll
                for (int mf = 0; mf < 2; ++mf)
                    ldsm4(a[mf],
                          Ts + at * kAterm + (arow + mf * 16) * kRowB + koA);
                const int nbt = 3 - at;     // products with at+bt<=2
#pragma unroll
                for (int bt = 0; bt < 3; ++bt) {
                    if (bt >= nbt) break;
#pragma unroll
                    for (int j = 0; j < 5; ++j) {
                        uint32_t b[4];
                        ldsm4(b, Bs + bt * kBterm + (brow + j * 16) * kRowB + koB);
#pragma unroll
                        for (int mf = 0; mf < 2; ++mf) {
                            mma16816(acc[mf][2 * j],     a[mf], b[0], b[1]);
                            mma16816(acc[mf][2 * j + 1], a[mf], b[2], b[3]);
                        }
                    }
                }
            }
        }
        __syncthreads();
        if (c + 1 < kChunks) {              // B has no prefetch (single buffer)
            load_B(c + 1, nbase, Bs, tid);
            cpa_commit();
        }
        if (c + 2 < kChunks) {              // A prefetch into freed buffer
            load_A(c + 2, m0, (c & 1) ? A1 : A0, tid);
            cpa_commit();
        }
    }

    // ---- fused bias + argmax over this warp's 80 cols ----
#pragma unroll
    for (int mf = 0; mf < 2; ++mf) {
#pragma unroll
        for (int hi = 0; hi < 2; ++hi) {
            float bv = -3.4e38f;
            int bi = 0;
#pragma unroll
            for (int nf = 0; nf < 10; ++nf) {
#pragma unroll
                for (int cc = 0; cc < 2; ++cc) {
                    int col = nw * 80 + nf * 8 + tig * 2 + cc;
                    float v = acc[mf][nf][hi * 2 + cc] + bias_s[col];
                    if (v > bv) { bv = v; bi = col; }
                }
            }
#pragma unroll
            for (int d = 1; d < 4; d <<= 1) {
                float ov = __shfl_xor_sync(0xFFFFFFFFu, bv, d);
                int   oi = __shfl_xor_sync(0xFFFFFFFFu, bi, d);
                if (ov > bv || (ov == bv && oi < bi)) { bv = ov; bi = oi; }
            }
            if (tig == 0) {
                int row = mw * 32 + mf * 16 + hi * 8 + gID;
                red_val[row * 4 + nw] = bv;
                red_idx[row * 4 + nw] = bi;
            }
        }
    }
    __syncthreads();

    // ---- final per-token argmax + histogram ----
    if (tid < kMT) {
        float bv = -3.4e38f; int bi = 0x7fffffff;
#pragma unroll
        for (int w = 0; w < 4; ++w) {
            float v = red_val[tid * 4 + w];
            int   i = red_idx[tid * 4 + w];
            if (v > bv || (v == bv && i < bi)) { bv = v; bi = i; }
        }
        idx_s[tid] = bi;
        atomicAdd(&g_counts[g * kV + bi], 1);
    }
    __syncthreads();

    // ---- coalesced codevector gather (this group's half of each out row) ----
    const float4* cbv  = (const float4*)cb;
    float4*       outv = (float4*)out;
#pragma unroll
    for (int i = 0; i < 8; ++i) {
        int e = tid + i * kThr;             // 0..2047
        int m = e >> 5, j = e & 31;
        int vi = idx_s[m];
        outv[(size_t)(m0 + m) * 64 + g * 32 + j] =
            cbv[(size_t)(g * kV + vi) * 32 + j];
    }
}

// ---------------- tiny kernels ----------------
__global__ void vq_zero() {
    if (threadIdx.x < kGV) g_counts[threadIdx.x] = 0;
}

__global__ void vq_ppl(float* __restrict__ out, int out_size) {
    __shared__ float terms[kGV];
    int t = threadIdx.x;               // 320 threads
    for (int g = 0; g < kG; g++) {
        float m = (float)g_counts[g * kV + t] / (float)kBT;
        terms[g * kV + t] = m * logf(m + 1e-7f);
    }
    __syncthreads();
    if (t == 0) {
        float p = 0.f;
        for (int g = 0; g < kG; g++) {
            float s = 0.f;
            for (int v = 0; v < kV; v++) s += terms[g * kV + v];
            p += expf(-s);
        }
        out[out_size - 1] = p;
    }
}

extern "C" void kernel_launch(void* const* d_in, const int* in_sizes, int n_in,
                              void* d_out, int out_size) {
    (void)in_sizes; (void)n_in;
    const float* hid  = (const float*)d_in[0];
    const float* W    = (const float*)d_in[1];
    const float* bias = (const float*)d_in[2];
    const float* cb   = (const float*)d_in[3];
    float* out = (float*)d_out;

    cudaFuncSetAttribute(vq_mma, cudaFuncAttributeMaxDynamicSharedMemorySize,
                         kSmemBytes);

    vq_zero<<<1, kGV>>>();
    split_h_kernel<<<(kBT * kH / 4) / 256, 256>>>(hid);
    split_w_kernel<<<(kH * kGV) / 256, 256>>>(W);
    vq_mma<<<(kBT / kMT) * kG, kThr, kSmemBytes>>>(bias, cb, out);
    vq_ppl<<<1, kV>>>(out, out_size);
}

// round 10
// speedup vs baseline: 1.1275x; 1.1275x over previous
#include <cuda_runtime.h>
#include <cuda_bf16.h>
#include <cstdint>

// ---------------------------------------------------------------------------
// Wav2Vec2 Gumbel VQ via mma.sync bf16 (sm_100 baseline path).
//   logits = h @ W + b with bf16x3 split, 6 products (fp32-quality).
//   256-thread CTAs, tile 64x320 (full group), warp tile 32x80, 2 CTAs/SM.
//   A double-buffered, B single-buffered. at-innermost product order keeps
//   ldsm traffic minimal (42/warp/chunk) within a 128-reg budget.
//   Fused argmax + histogram + codevector gather.
// ---------------------------------------------------------------------------

namespace {
constexpr int kBT = 65536;
constexpr int kH  = 512;
constexpr int kV  = 320;
constexpr int kG  = 2;
constexpr int kGV = kG * kV;

constexpr int kMT = 64;                   // tokens per CTA
constexpr int kNT = 320;                  // logit cols per CTA (full group)
constexpr int kKC = 32;                   // K per chunk (2 mma k-steps)
constexpr int kChunks = kH / kKC;         // 16
constexpr int kThr = 256;                 // threads per CTA (8 warps)

constexpr uint32_t kRowB   = 80;                           // 32 bf16 + 16B pad
constexpr uint32_t kAterm  = kMT * kRowB;                  // 5120
constexpr uint32_t kBterm  = kNT * kRowB;                  // 25600
constexpr uint32_t kAbuf   = 3 * kAterm;                   // 15360 (one stage)
constexpr uint32_t kBbuf   = 3 * kBterm;                   // 76800 (single)
constexpr uint32_t kHdr    = 3584;        // red_val|red_idx|idx_s|bias_s
constexpr uint32_t kSmemBytes = kHdr + 2 * kAbuf + kBbuf;  // 111104 (x2 <= 222K)
}  // namespace

// global scratch (no cudaMalloc allowed)
__device__ __align__(256) __nv_bfloat16 g_h1[(size_t)kBT * kH];
__device__ __align__(256) __nv_bfloat16 g_h2[(size_t)kBT * kH];
__device__ __align__(256) __nv_bfloat16 g_h3[(size_t)kBT * kH];
__device__ __align__(256) __nv_bfloat16 g_w1t[kGV * kH];
__device__ __align__(256) __nv_bfloat16 g_w2t[kGV * kH];
__device__ __align__(256) __nv_bfloat16 g_w3t[kGV * kH];
__device__ int g_counts[kGV];

// ---------------- PTX helpers ----------------
__device__ __forceinline__ uint32_t smem_u32(const void* p) {
    uint32_t a;
    asm("{ .reg .u64 t; cvta.to.shared.u64 t, %1; cvt.u32.u64 %0, t; }"
        : "=r"(a) : "l"(p));
    return a;
}
__device__ __forceinline__ void cpa16(uint32_t s, const void* g) {
    asm volatile("cp.async.cg.shared.global [%0], [%1], 16;" :: "r"(s), "l"(g));
}
__device__ __forceinline__ void cpa_commit() {
    asm volatile("cp.async.commit_group;" ::: "memory");
}
__device__ __forceinline__ void ldsm4(uint32_t* d, uint32_t addr) {
    asm volatile("ldmatrix.sync.aligned.m8n8.x4.shared.b16 {%0,%1,%2,%3}, [%4];"
                 : "=r"(d[0]), "=r"(d[1]), "=r"(d[2]), "=r"(d[3]) : "r"(addr));
}
__device__ __forceinline__ void mma16816(float* c, const uint32_t* a,
                                         uint32_t b0, uint32_t b1) {
    asm volatile(
        "mma.sync.aligned.m16n8k16.row.col.f32.bf16.bf16.f32 "
        "{%0,%1,%2,%3}, {%4,%5,%6,%7}, {%8,%9}, {%0,%1,%2,%3};"
        : "+f"(c[0]), "+f"(c[1]), "+f"(c[2]), "+f"(c[3])
        : "r"(a[0]), "r"(a[1]), "r"(a[2]), "r"(a[3]), "r"(b0), "r"(b1));
}

// ---------------- split kernels ----------------
__device__ __forceinline__ uint32_t pk2(__nv_bfloat16 x, __nv_bfloat16 y) {
    return (uint32_t)__bfloat16_as_ushort(x) |
           ((uint32_t)__bfloat16_as_ushort(y) << 16);
}

__global__ void __launch_bounds__(256) split_h_kernel(const float* __restrict__ h) {
    size_t i = (size_t)blockIdx.x * 256 + threadIdx.x;   // one float4 each
    float4 x = ((const float4*)h)[i];
    float v[4] = {x.x, x.y, x.z, x.w};
    __nv_bfloat16 a[4], b[4], c[4];
#pragma unroll
    for (int j = 0; j < 4; j++) {
        a[j] = __float2bfloat16_rn(v[j]);
        float r = v[j] - __bfloat162float(a[j]);
        b[j] = __float2bfloat16_rn(r);
        float r2 = r - __bfloat162float(b[j]);
        c[j] = __float2bfloat16_rn(r2);
    }
    ((uint2*)g_h1)[i] = make_uint2(pk2(a[0], a[1]), pk2(a[2], a[3]));
    ((uint2*)g_h2)[i] = make_uint2(pk2(b[0], b[1]), pk2(b[2], b[3]));
    ((uint2*)g_h3)[i] = make_uint2(pk2(c[0], c[1]), pk2(c[2], c[3]));
}

__global__ void __launch_bounds__(256) split_w_kernel(const float* __restrict__ W) {
    int idx = blockIdx.x * 256 + threadIdx.x;   // over 512*640
    int k = idx / kGV;
    int n = idx - k * kGV;
    float v = W[idx];
    __nv_bfloat16 a = __float2bfloat16_rn(v);
    float r = v - __bfloat162float(a);
    __nv_bfloat16 b = __float2bfloat16_rn(r);
    float r2 = r - __bfloat162float(b);
    __nv_bfloat16 c = __float2bfloat16_rn(r2);
    size_t o = (size_t)n * kH + k;               // transposed [n][k]
    g_w1t[o] = a; g_w2t[o] = b; g_w3t[o] = c;
}

// ---------------- main tensor kernel loaders ----------------
__device__ __forceinline__ void load_A(int c, int m0, uint32_t dst, int tid) {
    // 3 terms x 64 rows x 4 x 16B = 768 cp.async (3 per thread)
#pragma unroll
    for (int t = 0; t < 3; ++t) {
        const __nv_bfloat16* hp = (t == 0) ? g_h1 : (t == 1) ? g_h2 : g_h3;
        int row = tid >> 2, cs = tid & 3;
        const void* gp = hp + ((size_t)(m0 + row) * kH + c * kKC + cs * 8);
        cpa16(dst + t * kAterm + row * kRowB + cs * 16, gp);
    }
}

__device__ __forceinline__ void load_B(int c, int nbase, uint32_t dst, int tid) {
    // 3 terms x 320 rows x 4 x 16B = 3840 cp.async (15 per thread)
#pragma unroll
    for (int t = 0; t < 3; ++t) {
        const __nv_bfloat16* wp = (t == 0) ? g_w1t : (t == 1) ? g_w2t : g_w3t;
#pragma unroll
        for (int i = 0; i < 5; ++i) {
            int idx = tid + i * kThr;        // 0..1279
            int row = idx >> 2, cs = idx & 3;
            const void* gp = wp + ((size_t)(nbase + row) * kH + c * kKC + cs * 8);
            cpa16(dst + t * kBterm + row * kRowB + cs * 16, gp);
        }
    }
}

__global__ void __launch_bounds__(kThr, 2)
vq_mma(const float* __restrict__ bias,
       const float* __restrict__ cb,      // [640][128]
       float* __restrict__ out)           // [BT][256]
{
    extern __shared__ __align__(256) char smem_raw[];
    const uint32_t sbase = smem_u32(smem_raw);
    float* red_val = (float*)smem_raw;                 // [64][4]
    int*   red_idx = (int*)(smem_raw + 1024);          // [64][4]
    int*   idx_s   = (int*)(smem_raw + 2048);          // [64]
    float* bias_s  = (float*)(smem_raw + 2304);        // [320]
    const uint32_t A0 = sbase + kHdr;                  // A buf 0
    const uint32_t A1 = A0 + kAbuf;                    // A buf 1
    const uint32_t Bs = A1 + kAbuf;                    // single B buf

    const int tid  = threadIdx.x;
    const int warp = tid >> 5;
    const int lane = tid & 31;
    const int mw   = warp >> 2;            // 0..1 (32 rows each)
    const int nw   = warp & 3;             // 0..3 (80 cols each)
    const int gID  = lane >> 2;
    const int tig  = lane & 3;
    const int g    = blockIdx.x & 1;
    const int m0   = (blockIdx.x >> 1) * kMT;
    const int nbase = g * kV;              // B row base (full group)

    for (int i = tid; i < kNT; i += kThr) bias_s[i] = bias[nbase + i];

    // prologue: group0 = A0+B0, group1 = A1
    load_A(0, m0, A0, tid);
    load_B(0, nbase, Bs, tid);
    cpa_commit();
    load_A(1, m0, A1, tid);
    cpa_commit();

    float acc[2][10][4];
#pragma unroll
    for (int mf = 0; mf < 2; ++mf)
#pragma unroll
        for (int nf = 0; nf < 10; ++nf)
#pragma unroll
            for (int q = 0; q < 4; ++q) acc[mf][nf][q] = 0.f;

    const int g2 = lane >> 3, rr = lane & 7;

    for (int c = 0; c < kChunks; ++c) {
        if (c < kChunks - 1)
            asm volatile("cp.async.wait_group 1;" ::: "memory");
        else
            asm volatile("cp.async.wait_group 0;" ::: "memory");
        __syncthreads();

        const uint32_t Ts = (c & 1) ? A1 : A0;

#pragma unroll
        for (int ks = 0; ks < 2; ++ks) {
            const uint32_t arow = (uint32_t)(mw * 32 + (g2 & 1) * 8 + rr);
            const uint32_t koA  = (uint32_t)(ks * 32 + (g2 >> 1) * 16);
            const uint32_t brow = (uint32_t)(nw * 80 + (g2 >> 1) * 8 + rr);
            const uint32_t koB  = (uint32_t)(ks * 32 + (g2 & 1) * 16);

            // Load ALL A fragments once per ks (6 ldsm; 24 regs live).
            uint32_t a[3][2][4];
#pragma unroll
            for (int t = 0; t < 3; ++t)
#pragma unroll
                for (int mf = 0; mf < 2; ++mf)
                    ldsm4(a[t][mf],
                          Ts + t * kAterm + (arow + mf * 16) * kRowB + koA);

            // bt -> j -> at: each b[4] ldsm feeds up to 6 MMAs, then dies.
#pragma unroll
            for (int bt = 0; bt < 3; ++bt) {
                const int nat = 3 - bt;     // products with at+bt<=2
#pragma unroll
                for (int j = 0; j < 5; ++j) {
                    uint32_t b[4];
                    ldsm4(b, Bs + bt * kBterm + (brow + j * 16) * kRowB + koB);
#pragma unroll
                    for (int at = 0; at < 3; ++at) {
                        if (at >= nat) break;
#pragma unroll
                        for (int mf = 0; mf < 2; ++mf) {
                            mma16816(acc[mf][2 * j],     a[at][mf], b[0], b[1]);
                            mma16816(acc[mf][2 * j + 1], a[at][mf], b[2], b[3]);
                        }
                    }
                }
            }
        }
        __syncthreads();
        if (c + 1 < kChunks) {              // B has no prefetch (single buffer)
            load_B(c + 1, nbase, Bs, tid);
            cpa_commit();
        }
        if (c + 2 < kChunks) {              // A prefetch into freed buffer
            load_A(c + 2, m0, (c & 1) ? A1 : A0, tid);
            cpa_commit();
        }
    }

    // ---- fused bias + argmax over this warp's 80 cols ----
#pragma unroll
    for (int mf = 0; mf < 2; ++mf) {
#pragma unroll
        for (int hi = 0; hi < 2; ++hi) {
            float bv = -3.4e38f;
            int bi = 0;
#pragma unroll
            for (int nf = 0; nf < 10; ++nf) {
#pragma unroll
                for (int cc = 0; cc < 2; ++cc) {
                    int col = nw * 80 + nf * 8 + tig * 2 + cc;
                    float v = acc[mf][nf][hi * 2 + cc] + bias_s[col];
                    if (v > bv) { bv = v; bi = col; }
                }
            }
#pragma unroll
            for (int d = 1; d < 4; d <<= 1) {
                float ov = __shfl_xor_sync(0xFFFFFFFFu, bv, d);
                int   oi = __shfl_xor_sync(0xFFFFFFFFu, bi, d);
                if (ov > bv || (ov == bv && oi < bi)) { bv = ov; bi = oi; }
            }
            if (tig == 0) {
                int row = mw * 32 + mf * 16 + hi * 8 + gID;
                red_val[row * 4 + nw] = bv;
                red_idx[row * 4 + nw] = bi;
            }
        }
    }
    __syncthreads();

    // ---- final per-token argmax + histogram ----
    if (tid < kMT) {
        float bv = -3.4e38f; int bi = 0x7fffffff;
#pragma unroll
        for (int w = 0; w < 4; ++w) {
            float v = red_val[tid * 4 + w];
            int   i = red_idx[tid * 4 + w];
            if (v > bv || (v == bv && i < bi)) { bv = v; bi = i; }
        }
        idx_s[tid] = bi;
        atomicAdd(&g_counts[g * kV + bi], 1);
    }
    __syncthreads();

    // ---- coalesced codevector gather (this group's half of each out row) ----
    const float4* cbv  = (const float4*)cb;
    float4*       outv = (float4*)out;
#pragma unroll
    for (int i = 0; i < 8; ++i) {
        int e = tid + i * kThr;             // 0..2047
        int m = e >> 5, j = e & 31;
        int vi = idx_s[m];
        outv[(size_t)(m0 + m) * 64 + g * 32 + j] =
            cbv[(size_t)(g * kV + vi) * 32 + j];
    }
}

// ---------------- tiny kernels ----------------
__global__ void vq_zero() {
    if (threadIdx.x < kGV) g_counts[threadIdx.x] = 0;
}

__global__ void vq_ppl(float* __restrict__ out, int out_size) {
    __shared__ float terms[kGV];
    int t = threadIdx.x;               // 320 threads
    for (int g = 0; g < kG; g++) {
        float m = (float)g_counts[g * kV + t] / (float)kBT;
        terms[g * kV + t] = m * logf(m + 1e-7f);
    }
    __syncthreads();
    if (t == 0) {
        float p = 0.f;
        for (int g = 0; g < kG; g++) {
            float s = 0.f;
            for (int v = 0; v < kV; v++) s += terms[g * kV + v];
            p += expf(-s);
        }
        out[out_size - 1] = p;
    }
}

extern "C" void kernel_launch(void* const* d_in, const int* in_sizes, int n_in,
                              void* d_out, int out_size) {
    (void)in_sizes; (void)n_in;
    const float* hid  = (const float*)d_in[0];
    const float* W    = (const float*)d_in[1];
    const float* bias = (const float*)d_in[2];
    const float* cb   = (const float*)d_in[3];
    float* out = (float*)d_out;

    cudaFuncSetAttribute(vq_mma, cudaFuncAttributeMaxDynamicSharedMemorySize,
                         kSmemBytes);

    vq_zero<<<1, kGV>>>();
    split_h_kernel<<<(kBT * kH / 4) / 256, 256>>>(hid);
    split_w_kernel<<<(kH * kGV) / 256, 256>>>(W);
    vq_mma<<<(kBT / kMT) * kG, kThr, kSmemBytes>>>(bias, cb, out);
    vq_ppl<<<1, kV>>>(out, out_size);
}